// round 13
// baseline (speedup 1.0000x reference)
#include <cuda_runtime.h>
#include <cuda_bf16.h>
#include <cuda_fp16.h>
#include <cstdint>

// Problem constants (fixed by the dataset)
#define NN 50000
#define EE 800000
#define FF 64
#define HH 128
#define CAP 96   // ELL capacity per row; deg ~ Poisson(16), P(deg>96) ~ 0

typedef unsigned long long ull;
typedef __nv_bfloat16 bf16;

// ---------------- scratch (static device globals; no allocations) -----------
// HALF gather planes carry ONE EXTRA ROW (index NN), all-zero forever:
// zero-initialized at module load, never written. ELL pad slots point at it.
__device__ int    g_cnt[NN];                // zero-init at load; re-zeroed by k_gemm
__device__ int2   g_meta[NN];               // {cnt4 (padded), dinv bits} per row
__device__ int    g_ell[(size_t)NN * CAP];  // PRE-SHIFTED: col*FF element offset
__device__ __half g_XSh[(size_t)(NN + 1) * FF];  // half(dinv*X)   gather plane
__device__ __half g_T1h[(size_t)(NN + 1) * FF];  // half(dinv*T1)  gather plane
__device__ __half g_T2h[(size_t)(NN + 1) * FF];  // half(dinv*T2)  gather plane
__device__ float  g_T1S[(size_t)NN * FF];   // dinv * T1 (f32, exact)
__device__ float  g_T2S[(size_t)NN * FF];   // dinv * T2 (f32, exact)
__device__ float  g_T3f[(size_t)NN * FF];   // T3 (f32)
__device__ bf16 g_Bhi[128 * 256];           // B^T hi  [h][kidx]
__device__ bf16 g_Blo[128 * 256];           // B^T lo

// ---------------- helpers ----------------------------------------------------
__device__ __forceinline__ float tanh_ap(float x) {
    float r;
    asm("tanh.approx.f32 %0, %1;" : "=f"(r) : "f"(x));
    return r;
}
__device__ __forceinline__ uint32_t hadd2(uint32_t a, uint32_t b) {
    uint32_t r;
    asm("add.f16x2 %0, %1, %2;" : "=r"(r) : "r"(a), "r"(b));
    return r;
}

__device__ __forceinline__ void mma16816(float& d0, float& d1, float& d2, float& d3,
                                         uint32_t a0, uint32_t a1, uint32_t a2, uint32_t a3,
                                         uint32_t b0, uint32_t b1) {
    asm volatile(
        "mma.sync.aligned.m16n8k16.row.col.f32.bf16.bf16.f32 "
        "{%0,%1,%2,%3}, {%4,%5,%6,%7}, {%8,%9}, {%0,%1,%2,%3};"
        : "+f"(d0), "+f"(d1), "+f"(d2), "+f"(d3)
        : "r"(a0), "r"(a1), "r"(a2), "r"(a3), "r"(b0), "r"(b1));
}

// split f32 pair -> packed bf16x2 hi and lo
__device__ __forceinline__ void split_hilo(float x, float y,
                                           uint32_t& hp, uint32_t& lp) {
    bf16 h0 = __float2bfloat16(x), h1 = __float2bfloat16(y);
    bf16 l0 = __float2bfloat16(x - __bfloat162float(h0));
    bf16 l1 = __float2bfloat16(y - __bfloat162float(h1));
    hp = (uint32_t)__bfloat16_as_ushort(h0) | ((uint32_t)__bfloat16_as_ushort(h1) << 16);
    lp = (uint32_t)__bfloat16_as_ushort(l0) | ((uint32_t)__bfloat16_as_ushort(l1) << 16);
}

// pack float4 -> 4 halfs in a u64
__device__ __forceinline__ ull pack_h4(float4 v) {
    __half2 p01 = __float22half2_rn(make_float2(v.x, v.y));
    __half2 p23 = __float22half2_rn(make_float2(v.z, v.w));
    ull r;
    uint32_t lo = *(uint32_t*)&p01, hi = *(uint32_t*)&p23;
    asm("mov.b64 %0, {%1, %2};" : "=l"(r) : "r"(lo), "r"(hi));
    return r;
}

// ---------------- graph build ------------------------------------------------
// NOTE: g_cnt is zero on entry to every call: zero-initialized at module load,
// and re-zeroed at the head of k_gemm (which runs after all g_cnt consumers;
// gemm itself only reads g_meta/g_ell).
__global__ void k_fill(const int* __restrict__ ei) {
    int e = blockIdx.x * blockDim.x + threadIdx.x;
    if (e >= EE) return;
    int r = ei[e];
    int c = ei[EE + e];
    int s = atomicAdd(&g_cnt[r], 1);
    if (s < CAP) g_ell[(size_t)r * CAP + s] = c * FF;   // pre-shifted offset
}

// combo: blocks [0, 6250): meta{cnt4,dinv} + XSh = half(dinv*X) + ELL pad
//        blocks [6250, 6378): B^T hi/lo precompute from cheb_w
#define SCALE_BLOCKS 6250
__global__ void k_prep(const float* __restrict__ x, const float* __restrict__ W) {
    int tid = threadIdx.x;
    if (blockIdx.x < SCALE_BLOCKS) {
        int row  = blockIdx.x * 8 + (tid >> 5);
        int lane = tid & 31;
        int cnt = g_cnt[row];
        float d = (cnt > 0) ? rsqrtf((float)cnt) : 0.0f;
        int c = cnt < CAP ? cnt : CAP;
        int pe = (c + 3) & ~3;
        if (lane == 0) g_meta[row] = make_int2(pe, __float_as_int(d));
        // pad ELL row to multiple of 4 with pointers to the zero row (NN)
        if (lane < pe - c) g_ell[(size_t)row * CAP + c + lane] = NN * FF;
        int l2 = lane * 2;
        size_t idx = (size_t)row * FF + l2;
        float2 v = *(const float2*)(x + idx);
        __half2 h = __float22half2_rn(make_float2(v.x * d, v.y * d));
        *(__half2*)(g_XSh + idx) = h;
    } else {
        int idx = (blockIdx.x - SCALE_BLOCKS) * 256 + tid;  // 0..32767
        int h = idx >> 8, kidx = idx & 255;
        int k4 = kidx >> 6, f = kidx & 63;
        float w = W[k4 * (FF * HH) + f * HH + h];
        bf16 hi = __float2bfloat16(w);
        bf16 lo = __float2bfloat16(w - __bfloat162float(hi));
        g_Bhi[h * 256 + kidx] = hi;
        g_Blo[h * 256 + kidx] = lo;
    }
}

// ---------------- SPMM: TWO rows per warp, HALF gather + HADD2 trees ---------
// lanes 0-15 -> row 2w, lanes 16-31 -> row 2w+1; each lane owns 4 features.
// Each 4-neighbor group is tree-summed in packed f16x2 (6 HADD2), converted
// ONCE to f32 (2 cvt) and accumulated into a f32 master acc (4 FADD) — half
// the non-load issue work of per-neighbor conversion. Master acc stays f32.
//   P1: T1S = -d^2 * S(XSh);            also T1h = half(T1S)
//   P2: T2S = d*fma(-2d, S(T1h), -X);   also T2h = half(T2S)
//   P3: T3  = fma(-2d, S(T2h), -T1S*rdeg)
template <int PHASE>
__global__ __launch_bounds__(256, 6)
void k_spmm(const float* __restrict__ x) {
    int warp = (blockIdx.x * blockDim.x + threadIdx.x) >> 5;
    int lane = threadIdx.x & 31;
    int row  = warp * 2 + (lane >> 4);
    if (row >= NN) return;
    int l4 = (lane & 15) * 4;

    const __half* __restrict__ srcH = (PHASE == 1) ? g_XSh
                                    : (PHASE == 2) ? g_T1h : g_T2h;

    int2 mt = g_meta[row];
    int cnt4 = mt.x;
    float d = __int_as_float(mt.y);
    const int* ep = g_ell + (size_t)row * CAP;
    const __half* srcL = srcH + l4;            // lane-adjusted base

    float4 acc = make_float4(0.f, 0.f, 0.f, 0.f);
    for (int i = 0; i < cnt4; i += 4) {
        int4 c = *(const int4*)(ep + i);
        uint2 v0 = *(const uint2*)(srcL + c.x);
        uint2 v1 = *(const uint2*)(srcL + c.y);
        uint2 v2 = *(const uint2*)(srcL + c.z);
        uint2 v3 = *(const uint2*)(srcL + c.w);
        uint32_t slo = hadd2(hadd2(v0.x, v1.x), hadd2(v2.x, v3.x));
        uint32_t shi = hadd2(hadd2(v0.y, v1.y), hadd2(v2.y, v3.y));
        float2 flo = __half22float2(*(__half2*)&slo);
        float2 fhi = __half22float2(*(__half2*)&shi);
        acc.x += flo.x; acc.y += flo.y;
        acc.z += fhi.x; acc.w += fhi.y;
    }

    size_t idx = (size_t)row * FF + l4;
    float4 res;
    if (PHASE == 1) {
        float m = -d * d;                      // store dinv*T1 directly
        res.x = m * acc.x; res.y = m * acc.y;
        res.z = m * acc.z; res.w = m * acc.w;
        *(float4*)(g_T1S + idx) = res;
        *(ull*)(g_T1h + idx) = pack_h4(res);
    } else if (PHASE == 2) {
        float4 p = *(const float4*)(x + idx);  // prev = X (raw input)
        float m = -2.f * d;
        res.x = d * fmaf(m, acc.x, -p.x);      // store dinv*T2
        res.y = d * fmaf(m, acc.y, -p.y);
        res.z = d * fmaf(m, acc.z, -p.z);
        res.w = d * fmaf(m, acc.w, -p.w);
        *(float4*)(g_T2S + idx) = res;
        *(ull*)(g_T2h + idx) = pack_h4(res);
    } else {
        float rd = (d > 0.f) ? __frcp_rn(d) : 0.f;   // rdeg = 1/dinv
        float4 p = *(const float4*)(g_T1S + idx);    // prev = T1 = T1S*rdeg
        float m = -2.f * d;
        res.x = fmaf(m, acc.x, -p.x * rd);
        res.y = fmaf(m, acc.y, -p.y * rd);
        res.z = fmaf(m, acc.z, -p.z * rd);
        res.w = fmaf(m, acc.w, -p.w * rd);
        *(float4*)(g_T3f + idx) = res;
    }
}

// ---------------- HMMA GEMM + bias + tanh + final dot ------------------------
// out[n,h] = sum_k [X|T1|T2|T3][n,:] @ W[:,h] + b[h]; y[n]=sum_h tanh(out)*fw+fb
// bf16 hi/lo split: AhiBhi + AhiBlo + AloBhi. A staged from f32 arrays
// (X raw, T1S/T2S un-scaled by rdeg, T3 raw), hi/lo split in registers.
// ALSO: re-zeros g_cnt for the next kernel_launch call (replay invariant).
#define SA 72                      // smem row stride in elements (144 B)
#define OFF_AH 0
#define OFF_AL (128 * SA * 2)      // 18432
#define OFF_BH (2 * 128 * SA * 2)
#define OFF_BL (3 * 128 * SA * 2)
#define OFF_BIAS (4 * 128 * SA * 2)        // 73728
#define OFF_FW   (OFF_BIAS + 512)
#define OFF_OUT  (OFF_FW + 512)
#define SMEM_DYN (OFF_OUT + 512)

// one K=64 chunk of MMAs: AhiBhi + AhiBlo + AloBhi over 4 k-slices
__device__ __forceinline__ void mma_chunk(char* smem, int wm, int wn, int g, int t,
                                          float (&acc)[4][4][4]) {
#pragma unroll
    for (int ks = 0; ks < 4; ks++) {
        int k0 = ks * 16;
        uint32_t af[4][4], bh[4][2], bl[4][2];
#pragma unroll
        for (int mt = 0; mt < 4; mt++) {
            int r = wm * 64 + mt * 16 + g;
            const char* p = smem + OFF_AH;
            af[mt][0] = *(const uint32_t*)(p + (r * SA + k0 + t * 2) * 2);
            af[mt][1] = *(const uint32_t*)(p + ((r + 8) * SA + k0 + t * 2) * 2);
            af[mt][2] = *(const uint32_t*)(p + (r * SA + k0 + t * 2 + 8) * 2);
            af[mt][3] = *(const uint32_t*)(p + ((r + 8) * SA + k0 + t * 2 + 8) * 2);
        }
#pragma unroll
        for (int nt = 0; nt < 4; nt++) {
            int c = wn * 32 + nt * 8 + g;
            bh[nt][0] = *(const uint32_t*)(smem + OFF_BH + (c * SA + k0 + t * 2) * 2);
            bh[nt][1] = *(const uint32_t*)(smem + OFF_BH + (c * SA + k0 + t * 2 + 8) * 2);
            bl[nt][0] = *(const uint32_t*)(smem + OFF_BL + (c * SA + k0 + t * 2) * 2);
            bl[nt][1] = *(const uint32_t*)(smem + OFF_BL + (c * SA + k0 + t * 2 + 8) * 2);
        }
#pragma unroll
        for (int mt = 0; mt < 4; mt++)
#pragma unroll
            for (int nt = 0; nt < 4; nt++)
                mma16816(acc[mt][nt][0], acc[mt][nt][1], acc[mt][nt][2], acc[mt][nt][3],
                         af[mt][0], af[mt][1], af[mt][2], af[mt][3],
                         bh[nt][0], bh[nt][1]);
#pragma unroll
        for (int mt = 0; mt < 4; mt++)
#pragma unroll
            for (int nt = 0; nt < 4; nt++)
                mma16816(acc[mt][nt][0], acc[mt][nt][1], acc[mt][nt][2], acc[mt][nt][3],
                         af[mt][0], af[mt][1], af[mt][2], af[mt][3],
                         bl[nt][0], bl[nt][1]);
#pragma unroll
        for (int mt = 0; mt < 4; mt++) {
            int r = wm * 64 + mt * 16 + g;
            const char* p = smem + OFF_AL;
            af[mt][0] = *(const uint32_t*)(p + (r * SA + k0 + t * 2) * 2);
            af[mt][1] = *(const uint32_t*)(p + ((r + 8) * SA + k0 + t * 2) * 2);
            af[mt][2] = *(const uint32_t*)(p + (r * SA + k0 + t * 2 + 8) * 2);
            af[mt][3] = *(const uint32_t*)(p + ((r + 8) * SA + k0 + t * 2 + 8) * 2);
        }
#pragma unroll
        for (int mt = 0; mt < 4; mt++)
#pragma unroll
            for (int nt = 0; nt < 4; nt++)
                mma16816(acc[mt][nt][0], acc[mt][nt][1], acc[mt][nt][2], acc[mt][nt][3],
                         af[mt][0], af[mt][1], af[mt][2], af[mt][3],
                         bh[nt][0], bh[nt][1]);
    }
}

__global__ __launch_bounds__(256)
void k_gemm(const float* __restrict__ x,
            const float* __restrict__ bias, const float* __restrict__ fw,
            const float* __restrict__ fb, float* __restrict__ y) {
    extern __shared__ char smem[];
    int tid  = threadIdx.x;
    int lane = tid & 31, wid = tid >> 5;
    int wm = wid >> 2, wn = wid & 3;        // warp grid 2x4
    int g = lane >> 2, t = lane & 3;        // mma groupID / threadID-in-group
    int rowBase = blockIdx.x * 128;

    // re-zero g_cnt for next call (only fill/prep consume it; gemm uses g_meta)
    int zi = blockIdx.x * 256 + tid;
    if (zi < NN) g_cnt[zi] = 0;

    if (tid < 128) {
        *(float*)(smem + OFF_BIAS + tid * 4) = bias[tid];
        *(float*)(smem + OFF_FW   + tid * 4) = fw[tid];
        *(float*)(smem + OFF_OUT  + tid * 4) = 0.f;
    }

    float acc[4][4][4];
#pragma unroll
    for (int a = 0; a < 4; a++)
#pragma unroll
        for (int b = 0; b < 4; b++)
#pragma unroll
            for (int c = 0; c < 4; c++) acc[a][b][c] = 0.f;

    const float* Asrc[4] = {x, g_T1S, g_T2S, g_T3f};

    for (int ch = 0; ch < 4; ch++) {
        __syncthreads();
        const float* asrc = Asrc[ch];
        bool needR = (ch == 1) || (ch == 2);   // un-scale T1S/T2S by rdeg
#pragma unroll
        for (int rep = 0; rep < 4; rep++) {
            int u = rep * 256 + tid;
            int r = u >> 3, j = u & 7;         // row r, 8-elem group j
            int grow = rowBase + r;
            float4 a0 = make_float4(0.f, 0.f, 0.f, 0.f), a1 = a0;
            float sc = 1.f;
            if (grow < NN) {
                const float* p = asrc + (size_t)grow * FF + j * 8;
                a0 = *(const float4*)(p);
                a1 = *(const float4*)(p + 4);
                if (needR) {
                    float dv = __int_as_float(g_meta[grow].y);
                    sc = (dv > 0.f) ? __frcp_rn(dv) : 0.f;
                }
            }
            uint4 vh, vl;
            split_hilo(sc * a0.x, sc * a0.y, vh.x, vl.x);
            split_hilo(sc * a0.z, sc * a0.w, vh.y, vl.y);
            split_hilo(sc * a1.x, sc * a1.y, vh.z, vl.z);
            split_hilo(sc * a1.z, sc * a1.w, vh.w, vl.w);
            *(uint4*)(smem + OFF_AH + r * 144 + j * 16) = vh;
            *(uint4*)(smem + OFF_AL + r * 144 + j * 16) = vl;
            uint4 bh = *(const uint4*)(g_Bhi + r * 256 + ch * 64 + j * 8);
            uint4 bl = *(const uint4*)(g_Blo + r * 256 + ch * 64 + j * 8);
            *(uint4*)(smem + OFF_BH + r * 144 + j * 16) = bh;
            *(uint4*)(smem + OFF_BL + r * 144 + j * 16) = bl;
        }
        __syncthreads();
        mma_chunk(smem, wm, wn, g, t, acc);
    }
    __syncthreads();

    // epilogue: tanh(acc + bias) * fw, reduce cols -> sm_out rows
    const float* sBias = (const float*)(smem + OFF_BIAS);
    const float* sFw   = (const float*)(smem + OFF_FW);
    float* sOut        = (float*)(smem + OFF_OUT);
#pragma unroll
    for (int mt = 0; mt < 4; mt++) {
#pragma unroll
        for (int rr = 0; rr < 2; rr++) {
            int rloc = wm * 64 + mt * 16 + g + rr * 8;
            float p = 0.f;
#pragma unroll
            for (int nt = 0; nt < 4; nt++) {
#pragma unroll
                for (int cc = 0; cc < 2; cc++) {
                    int col = wn * 32 + nt * 8 + t * 2 + cc;
                    float v = acc[mt][nt][rr * 2 + cc];
                    p += tanh_ap(v + sBias[col]) * sFw[col];
                }
            }
            p += __shfl_xor_sync(0xffffffffu, p, 1);
            p += __shfl_xor_sync(0xffffffffu, p, 2);
            if (t == 0) atomicAdd(&sOut[rloc], p);
        }
    }
    __syncthreads();
    if (tid < 128) {
        int r = rowBase + tid;
        if (r < NN) y[r] = sOut[tid] + fb[0];
    }
}

// ---------------- launch -----------------------------------------------------
extern "C" void kernel_launch(void* const* d_in, const int* in_sizes, int n_in,
                              void* d_out, int out_size) {
    const float* features = (const float*)d_in[0];
    const int*   ei       = (const int*)d_in[1];
    const float* cheb_w   = (const float*)d_in[2];
    const float* cheb_b   = (const float*)d_in[3];
    const float* final_w  = (const float*)d_in[4];
    const float* final_b  = (const float*)d_in[5];
    float* y = (float*)d_out;

    static bool attr_set = false;
    if (!attr_set) {
        cudaFuncSetAttribute(k_gemm, cudaFuncAttributeMaxDynamicSharedMemorySize,
                             SMEM_DYN);
        attr_set = true;
    }

    k_fill<<<(EE + 255) / 256, 256>>>(ei);
    k_prep<<<SCALE_BLOCKS + 128, 256>>>(features, cheb_w);

    int spmm_blocks = (NN / 2 + 7) / 8;      // 2 rows per warp, 8 warps per block
    k_spmm<1><<<spmm_blocks, 256>>>(features);
    k_spmm<2><<<spmm_blocks, 256>>>(features);   // profiled slot (4th launch)
    k_spmm<3><<<spmm_blocks, 256>>>(features);

    k_gemm<<<(NN + 127) / 128, 256, SMEM_DYN>>>(features, cheb_b, final_w,
                                                final_b, y);
}

// round 14
// speedup vs baseline: 1.0065x; 1.0065x over previous
#include <cuda_runtime.h>
#include <cuda_bf16.h>
#include <cuda_fp16.h>
#include <cstdint>

// Problem constants (fixed by the dataset)
#define NN 50000
#define EE 800000
#define FF 64
#define HH 128
#define CAP 96   // ELL capacity per row; deg ~ Poisson(16), P(deg>96) ~ 0

typedef unsigned long long ull;
typedef __nv_bfloat16 bf16;

// ---------------- scratch (static device globals; no allocations) -----------
// HALF gather planes carry ONE EXTRA ROW (index NN), all-zero forever:
// zero-initialized at module load, never written. ELL pad slots point at it.
__device__ int    g_cnt[NN];                // zero-init at load; re-zeroed by k_gemm
__device__ int2   g_meta[NN];               // {cnt4 (padded), dinv bits} per row
__device__ int    g_ell[(size_t)NN * CAP];  // PRE-SHIFTED: col*FF element offset
__device__ __half g_XSh[(size_t)(NN + 1) * FF];  // half(dinv*X)   gather plane
__device__ __half g_T1h[(size_t)(NN + 1) * FF];  // half(dinv*T1)  gather plane
__device__ __half g_T2h[(size_t)(NN + 1) * FF];  // half(dinv*T2)  gather plane
__device__ float  g_T1S[(size_t)NN * FF];   // dinv * T1 (f32, exact)
__device__ float  g_T2S[(size_t)NN * FF];   // dinv * T2 (f32, exact)
__device__ float  g_T3f[(size_t)NN * FF];   // T3 (f32)
__device__ bf16 g_Bhi[128 * 256];           // B^T hi  [h][kidx]
__device__ bf16 g_Blo[128 * 256];           // B^T lo

// ---------------- helpers ----------------------------------------------------
__device__ __forceinline__ float tanh_ap(float x) {
    float r;
    asm("tanh.approx.f32 %0, %1;" : "=f"(r) : "f"(x));
    return r;
}

__device__ __forceinline__ void mma16816(float& d0, float& d1, float& d2, float& d3,
                                         uint32_t a0, uint32_t a1, uint32_t a2, uint32_t a3,
                                         uint32_t b0, uint32_t b1) {
    asm volatile(
        "mma.sync.aligned.m16n8k16.row.col.f32.bf16.bf16.f32 "
        "{%0,%1,%2,%3}, {%4,%5,%6,%7}, {%8,%9}, {%0,%1,%2,%3};"
        : "+f"(d0), "+f"(d1), "+f"(d2), "+f"(d3)
        : "r"(a0), "r"(a1), "r"(a2), "r"(a3), "r"(b0), "r"(b1));
}

// split f32 pair -> packed bf16x2 hi and lo
__device__ __forceinline__ void split_hilo(float x, float y,
                                           uint32_t& hp, uint32_t& lp) {
    bf16 h0 = __float2bfloat16(x), h1 = __float2bfloat16(y);
    bf16 l0 = __float2bfloat16(x - __bfloat162float(h0));
    bf16 l1 = __float2bfloat16(y - __bfloat162float(h1));
    hp = (uint32_t)__bfloat16_as_ushort(h0) | ((uint32_t)__bfloat16_as_ushort(h1) << 16);
    lp = (uint32_t)__bfloat16_as_ushort(l0) | ((uint32_t)__bfloat16_as_ushort(l1) << 16);
}

// accumulate 4 halfs (packed in a u64) into a float4
__device__ __forceinline__ void acc_h4(float4& a, ull v) {
    __half2 p01 = *(__half2*)&v;
    __half2 p23 = *((__half2*)&v + 1);
    float2 f01 = __half22float2(p01);
    float2 f23 = __half22float2(p23);
    a.x += f01.x; a.y += f01.y; a.z += f23.x; a.w += f23.y;
}
// pack float4 -> 4 halfs in a u64
__device__ __forceinline__ ull pack_h4(float4 v) {
    __half2 p01 = __float22half2_rn(make_float2(v.x, v.y));
    __half2 p23 = __float22half2_rn(make_float2(v.z, v.w));
    ull r;
    uint32_t lo = *(uint32_t*)&p01, hi = *(uint32_t*)&p23;
    asm("mov.b64 %0, {%1, %2};" : "=l"(r) : "r"(lo), "r"(hi));
    return r;
}

// ---------------- graph build ------------------------------------------------
// NOTE: g_cnt is zero on entry to every call: zero-initialized at module load,
// and re-zeroed at the head of k_gemm (which runs after all g_cnt consumers;
// gemm itself only reads g_meta/g_ell).
__global__ void k_fill(const int* __restrict__ ei) {
    int e = blockIdx.x * blockDim.x + threadIdx.x;
    if (e >= EE) return;
    int r = ei[e];
    int c = ei[EE + e];
    int s = atomicAdd(&g_cnt[r], 1);
    if (s < CAP) g_ell[(size_t)r * CAP + s] = c * FF;   // pre-shifted offset
}

// combo: blocks [0, 6250): meta{cnt4,dinv} + XSh = half(dinv*X) + ELL pad
//        blocks [6250, 6378): B^T hi/lo precompute from cheb_w
#define SCALE_BLOCKS 6250
__global__ void k_prep(const float* __restrict__ x, const float* __restrict__ W) {
    int tid = threadIdx.x;
    if (blockIdx.x < SCALE_BLOCKS) {
        int row  = blockIdx.x * 8 + (tid >> 5);
        int lane = tid & 31;
        int cnt = g_cnt[row];
        float d = (cnt > 0) ? rsqrtf((float)cnt) : 0.0f;
        int c = cnt < CAP ? cnt : CAP;
        int pe = (c + 3) & ~3;
        if (lane == 0) g_meta[row] = make_int2(pe, __float_as_int(d));
        // pad ELL row to multiple of 4 with pointers to the zero row (NN)
        if (lane < pe - c) g_ell[(size_t)row * CAP + c + lane] = NN * FF;
        int l2 = lane * 2;
        size_t idx = (size_t)row * FF + l2;
        float2 v = *(const float2*)(x + idx);
        __half2 h = __float22half2_rn(make_float2(v.x * d, v.y * d));
        *(__half2*)(g_XSh + idx) = h;
    } else {
        int idx = (blockIdx.x - SCALE_BLOCKS) * 256 + tid;  // 0..32767
        int h = idx >> 8, kidx = idx & 255;
        int k4 = kidx >> 6, f = kidx & 63;
        float w = W[k4 * (FF * HH) + f * HH + h];
        bf16 hi = __float2bfloat16(w);
        bf16 lo = __float2bfloat16(w - __bfloat162float(hi));
        g_Bhi[h * 256 + kidx] = hi;
        g_Blo[h * 256 + kidx] = lo;
    }
}

// ---------------- SPMM: TWO rows per warp, HALF gather planes ----------------
// lanes 0-15 -> row 2w, lanes 16-31 -> row 2w+1; each lane owns 4 features.
// Gathers read half planes (128B/neighbor/row, LDG.64/lane); accumulate f32
// incrementally (R12 structure — overlaps converts with the load stream).
// __launch_bounds__(256,8): 32-reg budget -> 100% theoretical occupancy; the
// lean loop (8 load regs + 4 acc + addressing) should fit without spills.
//   P1: T1S = -d^2 * S(XSh);            also T1h = half(T1S)
//   P2: T2S = d*fma(-2d, S(T1h), -X);   also T2h = half(T2S)
//   P3: T3  = fma(-2d, S(T2h), -T1S*rdeg)
template <int PHASE>
__global__ __launch_bounds__(256, 8)
void k_spmm(const float* __restrict__ x) {
    int warp = (blockIdx.x * blockDim.x + threadIdx.x) >> 5;
    int lane = threadIdx.x & 31;
    int row  = warp * 2 + (lane >> 4);
    if (row >= NN) return;
    int l4 = (lane & 15) * 4;

    const __half* __restrict__ srcH = (PHASE == 1) ? g_XSh
                                    : (PHASE == 2) ? g_T1h : g_T2h;

    int2 mt = g_meta[row];
    int cnt4 = mt.x;
    float d = __int_as_float(mt.y);
    const int* ep = g_ell + (size_t)row * CAP;
    const __half* srcL = srcH + l4;            // lane-adjusted base

    float4 acc = make_float4(0.f, 0.f, 0.f, 0.f);
    for (int i = 0; i < cnt4; i += 4) {
        int4 c = *(const int4*)(ep + i);
        ull v0 = *(const ull*)(srcL + c.x);
        ull v1 = *(const ull*)(srcL + c.y);
        ull v2 = *(const ull*)(srcL + c.z);
        ull v3 = *(const ull*)(srcL + c.w);
        acc_h4(acc, v0);
        acc_h4(acc, v1);
        acc_h4(acc, v2);
        acc_h4(acc, v3);
    }

    size_t idx = (size_t)row * FF + l4;
    float4 res;
    if (PHASE == 1) {
        float m = -d * d;                      // store dinv*T1 directly
        res.x = m * acc.x; res.y = m * acc.y;
        res.z = m * acc.z; res.w = m * acc.w;
        *(float4*)(g_T1S + idx) = res;
        *(ull*)(g_T1h + idx) = pack_h4(res);
    } else if (PHASE == 2) {
        float4 p = *(const float4*)(x + idx);  // prev = X (raw input)
        float m = -2.f * d;
        res.x = d * fmaf(m, acc.x, -p.x);      // store dinv*T2
        res.y = d * fmaf(m, acc.y, -p.y);
        res.z = d * fmaf(m, acc.z, -p.z);
        res.w = d * fmaf(m, acc.w, -p.w);
        *(float4*)(g_T2S + idx) = res;
        *(ull*)(g_T2h + idx) = pack_h4(res);
    } else {
        float rd = (d > 0.f) ? __frcp_rn(d) : 0.f;   // rdeg = 1/dinv
        float4 p = *(const float4*)(g_T1S + idx);    // prev = T1 = T1S*rdeg
        float m = -2.f * d;
        res.x = fmaf(m, acc.x, -p.x * rd);
        res.y = fmaf(m, acc.y, -p.y * rd);
        res.z = fmaf(m, acc.z, -p.z * rd);
        res.w = fmaf(m, acc.w, -p.w * rd);
        *(float4*)(g_T3f + idx) = res;
    }
}

// ---------------- HMMA GEMM + bias + tanh + final dot ------------------------
// out[n,h] = sum_k [X|T1|T2|T3][n,:] @ W[:,h] + b[h]; y[n]=sum_h tanh(out)*fw+fb
// bf16 hi/lo split: AhiBhi + AhiBlo + AloBhi. A staged from f32 arrays
// (X raw, T1S/T2S un-scaled by rdeg, T3 raw), hi/lo split in registers.
// ALSO: re-zeros g_cnt for the next kernel_launch call (replay invariant).
#define SA 72                      // smem row stride in elements (144 B)
#define OFF_AH 0
#define OFF_AL (128 * SA * 2)      // 18432
#define OFF_BH (2 * 128 * SA * 2)
#define OFF_BL (3 * 128 * SA * 2)
#define OFF_BIAS (4 * 128 * SA * 2)        // 73728
#define OFF_FW   (OFF_BIAS + 512)
#define OFF_OUT  (OFF_FW + 512)
#define SMEM_DYN (OFF_OUT + 512)

// one K=64 chunk of MMAs: AhiBhi + AhiBlo + AloBhi over 4 k-slices
__device__ __forceinline__ void mma_chunk(char* smem, int wm, int wn, int g, int t,
                                          float (&acc)[4][4][4]) {
#pragma unroll
    for (int ks = 0; ks < 4; ks++) {
        int k0 = ks * 16;
        uint32_t af[4][4], bh[4][2], bl[4][2];
#pragma unroll
        for (int mt = 0; mt < 4; mt++) {
            int r = wm * 64 + mt * 16 + g;
            const char* p = smem + OFF_AH;
            af[mt][0] = *(const uint32_t*)(p + (r * SA + k0 + t * 2) * 2);
            af[mt][1] = *(const uint32_t*)(p + ((r + 8) * SA + k0 + t * 2) * 2);
            af[mt][2] = *(const uint32_t*)(p + (r * SA + k0 + t * 2 + 8) * 2);
            af[mt][3] = *(const uint32_t*)(p + ((r + 8) * SA + k0 + t * 2 + 8) * 2);
        }
#pragma unroll
        for (int nt = 0; nt < 4; nt++) {
            int c = wn * 32 + nt * 8 + g;
            bh[nt][0] = *(const uint32_t*)(smem + OFF_BH + (c * SA + k0 + t * 2) * 2);
            bh[nt][1] = *(const uint32_t*)(smem + OFF_BH + (c * SA + k0 + t * 2 + 8) * 2);
            bl[nt][0] = *(const uint32_t*)(smem + OFF_BL + (c * SA + k0 + t * 2) * 2);
            bl[nt][1] = *(const uint32_t*)(smem + OFF_BL + (c * SA + k0 + t * 2 + 8) * 2);
        }
#pragma unroll
        for (int mt = 0; mt < 4; mt++)
#pragma unroll
            for (int nt = 0; nt < 4; nt++)
                mma16816(acc[mt][nt][0], acc[mt][nt][1], acc[mt][nt][2], acc[mt][nt][3],
                         af[mt][0], af[mt][1], af[mt][2], af[mt][3],
                         bh[nt][0], bh[nt][1]);
#pragma unroll
        for (int mt = 0; mt < 4; mt++)
#pragma unroll
            for (int nt = 0; nt < 4; nt++)
                mma16816(acc[mt][nt][0], acc[mt][nt][1], acc[mt][nt][2], acc[mt][nt][3],
                         af[mt][0], af[mt][1], af[mt][2], af[mt][3],
                         bl[nt][0], bl[nt][1]);
#pragma unroll
        for (int mt = 0; mt < 4; mt++) {
            int r = wm * 64 + mt * 16 + g;
            const char* p = smem + OFF_AL;
            af[mt][0] = *(const uint32_t*)(p + (r * SA + k0 + t * 2) * 2);
            af[mt][1] = *(const uint32_t*)(p + ((r + 8) * SA + k0 + t * 2) * 2);
            af[mt][2] = *(const uint32_t*)(p + (r * SA + k0 + t * 2 + 8) * 2);
            af[mt][3] = *(const uint32_t*)(p + ((r + 8) * SA + k0 + t * 2 + 8) * 2);
        }
#pragma unroll
        for (int mt = 0; mt < 4; mt++)
#pragma unroll
            for (int nt = 0; nt < 4; nt++)
                mma16816(acc[mt][nt][0], acc[mt][nt][1], acc[mt][nt][2], acc[mt][nt][3],
                         af[mt][0], af[mt][1], af[mt][2], af[mt][3],
                         bh[nt][0], bh[nt][1]);
    }
}

__global__ __launch_bounds__(256)
void k_gemm(const float* __restrict__ x,
            const float* __restrict__ bias, const float* __restrict__ fw,
            const float* __restrict__ fb, float* __restrict__ y) {
    extern __shared__ char smem[];
    int tid  = threadIdx.x;
    int lane = tid & 31, wid = tid >> 5;
    int wm = wid >> 2, wn = wid & 3;        // warp grid 2x4
    int g = lane >> 2, t = lane & 3;        // mma groupID / threadID-in-group
    int rowBase = blockIdx.x * 128;

    // re-zero g_cnt for next call (only fill/prep consume it; gemm uses g_meta)
    int zi = blockIdx.x * 256 + tid;
    if (zi < NN) g_cnt[zi] = 0;

    if (tid < 128) {
        *(float*)(smem + OFF_BIAS + tid * 4) = bias[tid];
        *(float*)(smem + OFF_FW   + tid * 4) = fw[tid];
        *(float*)(smem + OFF_OUT  + tid * 4) = 0.f;
    }

    float acc[4][4][4];
#pragma unroll
    for (int a = 0; a < 4; a++)
#pragma unroll
        for (int b = 0; b < 4; b++)
#pragma unroll
            for (int c = 0; c < 4; c++) acc[a][b][c] = 0.f;

    const float* Asrc[4] = {x, g_T1S, g_T2S, g_T3f};

    for (int ch = 0; ch < 4; ch++) {
        __syncthreads();
        const float* asrc = Asrc[ch];
        bool needR = (ch == 1) || (ch == 2);   // un-scale T1S/T2S by rdeg
#pragma unroll
        for (int rep = 0; rep < 4; rep++) {
            int u = rep * 256 + tid;
            int r = u >> 3, j = u & 7;         // row r, 8-elem group j
            int grow = rowBase + r;
            float4 a0 = make_float4(0.f, 0.f, 0.f, 0.f), a1 = a0;
            float sc = 1.f;
            if (grow < NN) {
                const float* p = asrc + (size_t)grow * FF + j * 8;
                a0 = *(const float4*)(p);
                a1 = *(const float4*)(p + 4);
                if (needR) {
                    float dv = __int_as_float(g_meta[grow].y);
                    sc = (dv > 0.f) ? __frcp_rn(dv) : 0.f;
                }
            }
            uint4 vh, vl;
            split_hilo(sc * a0.x, sc * a0.y, vh.x, vl.x);
            split_hilo(sc * a0.z, sc * a0.w, vh.y, vl.y);
            split_hilo(sc * a1.x, sc * a1.y, vh.z, vl.z);
            split_hilo(sc * a1.z, sc * a1.w, vh.w, vl.w);
            *(uint4*)(smem + OFF_AH + r * 144 + j * 16) = vh;
            *(uint4*)(smem + OFF_AL + r * 144 + j * 16) = vl;
            uint4 bh = *(const uint4*)(g_Bhi + r * 256 + ch * 64 + j * 8);
            uint4 bl = *(const uint4*)(g_Blo + r * 256 + ch * 64 + j * 8);
            *(uint4*)(smem + OFF_BH + r * 144 + j * 16) = bh;
            *(uint4*)(smem + OFF_BL + r * 144 + j * 16) = bl;
        }
        __syncthreads();
        mma_chunk(smem, wm, wn, g, t, acc);
    }
    __syncthreads();

    // epilogue: tanh(acc + bias) * fw, reduce cols -> sm_out rows
    const float* sBias = (const float*)(smem + OFF_BIAS);
    const float* sFw   = (const float*)(smem + OFF_FW);
    float* sOut        = (float*)(smem + OFF_OUT);
#pragma unroll
    for (int mt = 0; mt < 4; mt++) {
#pragma unroll
        for (int rr = 0; rr < 2; rr++) {
            int rloc = wm * 64 + mt * 16 + g + rr * 8;
            float p = 0.f;
#pragma unroll
            for (int nt = 0; nt < 4; nt++) {
#pragma unroll
                for (int cc = 0; cc < 2; cc++) {
                    int col = wn * 32 + nt * 8 + t * 2 + cc;
                    float v = acc[mt][nt][rr * 2 + cc];
                    p += tanh_ap(v + sBias[col]) * sFw[col];
                }
            }
            p += __shfl_xor_sync(0xffffffffu, p, 1);
            p += __shfl_xor_sync(0xffffffffu, p, 2);
            if (t == 0) atomicAdd(&sOut[rloc], p);
        }
    }
    __syncthreads();
    if (tid < 128) {
        int r = rowBase + tid;
        if (r < NN) y[r] = sOut[tid] + fb[0];
    }
}

// ---------------- launch -----------------------------------------------------
extern "C" void kernel_launch(void* const* d_in, const int* in_sizes, int n_in,
                              void* d_out, int out_size) {
    const float* features = (const float*)d_in[0];
    const int*   ei       = (const int*)d_in[1];
    const float* cheb_w   = (const float*)d_in[2];
    const float* cheb_b   = (const float*)d_in[3];
    const float* final_w  = (const float*)d_in[4];
    const float* final_b  = (const float*)d_in[5];
    float* y = (float*)d_out;

    static bool attr_set = false;
    if (!attr_set) {
        cudaFuncSetAttribute(k_gemm, cudaFuncAttributeMaxDynamicSharedMemorySize,
                             SMEM_DYN);
        attr_set = true;
    }

    k_fill<<<(EE + 255) / 256, 256>>>(ei);
    k_prep<<<SCALE_BLOCKS + 128, 256>>>(features, cheb_w);

    int spmm_blocks = (NN / 2 + 7) / 8;      // 2 rows per warp, 8 warps per block
    k_spmm<1><<<spmm_blocks, 256>>>(features);
    k_spmm<2><<<spmm_blocks, 256>>>(features);   // profiled slot (4th launch)
    k_spmm<3><<<spmm_blocks, 256>>>(features);

    k_gemm<<<(NN + 127) / 128, 256, SMEM_DYN>>>(features, cheb_b, final_w,
                                                final_b, y);
}

// round 15
// speedup vs baseline: 1.0546x; 1.0478x over previous
#include <cuda_runtime.h>
#include <cuda_bf16.h>
#include <cuda_fp16.h>
#include <cstdint>

// Problem constants (fixed by the dataset)
#define NN 50000
#define EE 800000
#define FF 64
#define HH 128
#define CAP 96   // ELL capacity per row; deg ~ Poisson(16), P(deg>96) ~ 0

typedef unsigned long long ull;
typedef __nv_bfloat16 bf16;

// ---------------- scratch (static device globals; no allocations) -----------
// HALF planes are the ONLY T storage now. Gather planes carry ONE EXTRA ROW
// (index NN), all-zero forever (zero-init at load, never written); ELL pad
// slots point at it. bf16 hi/lo staging in k_gemm represents f16 EXACTLY.
__device__ int    g_cnt[NN];                // zero-init at load; re-zeroed by k_gemm
__device__ int2   g_meta[NN];               // {cnt4 (padded), dinv bits} per row
__device__ int    g_ell[(size_t)NN * CAP];  // PRE-SHIFTED: col*FF element offset
__device__ __half g_XSh[(size_t)(NN + 1) * FF];  // half(dinv*X)   gather plane
__device__ __half g_T1h[(size_t)(NN + 1) * FF];  // half(dinv*T1)  gather plane
__device__ __half g_T2h[(size_t)(NN + 1) * FF];  // half(dinv*T2)  gather plane
__device__ __half g_T3h[(size_t)NN * FF];        // half(T3), gemm input only
__device__ bf16 g_Bhi[128 * 256];           // B^T hi  [h][kidx]
__device__ bf16 g_Blo[128 * 256];           // B^T lo

// ---------------- helpers ----------------------------------------------------
__device__ __forceinline__ float tanh_ap(float x) {
    float r;
    asm("tanh.approx.f32 %0, %1;" : "=f"(r) : "f"(x));
    return r;
}

__device__ __forceinline__ void mma16816(float& d0, float& d1, float& d2, float& d3,
                                         uint32_t a0, uint32_t a1, uint32_t a2, uint32_t a3,
                                         uint32_t b0, uint32_t b1) {
    asm volatile(
        "mma.sync.aligned.m16n8k16.row.col.f32.bf16.bf16.f32 "
        "{%0,%1,%2,%3}, {%4,%5,%6,%7}, {%8,%9}, {%0,%1,%2,%3};"
        : "+f"(d0), "+f"(d1), "+f"(d2), "+f"(d3)
        : "r"(a0), "r"(a1), "r"(a2), "r"(a3), "r"(b0), "r"(b1));
}

// split f32 pair -> packed bf16x2 hi and lo
__device__ __forceinline__ void split_hilo(float x, float y,
                                           uint32_t& hp, uint32_t& lp) {
    bf16 h0 = __float2bfloat16(x), h1 = __float2bfloat16(y);
    bf16 l0 = __float2bfloat16(x - __bfloat162float(h0));
    bf16 l1 = __float2bfloat16(y - __bfloat162float(h1));
    hp = (uint32_t)__bfloat16_as_ushort(h0) | ((uint32_t)__bfloat16_as_ushort(h1) << 16);
    lp = (uint32_t)__bfloat16_as_ushort(l0) | ((uint32_t)__bfloat16_as_ushort(l1) << 16);
}

// accumulate 4 halfs (packed in a u64) into a float4
__device__ __forceinline__ void acc_h4(float4& a, ull v) {
    __half2 p01 = *(__half2*)&v;
    __half2 p23 = *((__half2*)&v + 1);
    float2 f01 = __half22float2(p01);
    float2 f23 = __half22float2(p23);
    a.x += f01.x; a.y += f01.y; a.z += f23.x; a.w += f23.y;
}
// pack float4 -> 4 halfs in a u64
__device__ __forceinline__ ull pack_h4(float4 v) {
    __half2 p01 = __float22half2_rn(make_float2(v.x, v.y));
    __half2 p23 = __float22half2_rn(make_float2(v.z, v.w));
    ull r;
    uint32_t lo = *(uint32_t*)&p01, hi = *(uint32_t*)&p23;
    asm("mov.b64 %0, {%1, %2};" : "=l"(r) : "r"(lo), "r"(hi));
    return r;
}
// unpack 4 halfs (u64) -> float4
__device__ __forceinline__ float4 unpack_h4(ull v) {
    __half2 p01 = *(__half2*)&v;
    __half2 p23 = *((__half2*)&v + 1);
    float2 f01 = __half22float2(p01);
    float2 f23 = __half22float2(p23);
    return make_float4(f01.x, f01.y, f23.x, f23.y);
}

// ---------------- graph build ------------------------------------------------
// NOTE: g_cnt is zero on entry to every call: zero-initialized at module load,
// and re-zeroed at the head of k_gemm (which runs after all g_cnt consumers;
// gemm itself only reads g_meta/g_ell).
__global__ void k_fill(const int* __restrict__ ei) {
    int e = blockIdx.x * blockDim.x + threadIdx.x;
    if (e >= EE) return;
    int r = ei[e];
    int c = ei[EE + e];
    int s = atomicAdd(&g_cnt[r], 1);
    if (s < CAP) g_ell[(size_t)r * CAP + s] = c * FF;   // pre-shifted offset
}

// combo: blocks [0, 6250): meta{cnt4,dinv} + XSh = half(dinv*X) + ELL pad
//        blocks [6250, 6378): B^T hi/lo precompute from cheb_w
#define SCALE_BLOCKS 6250
__global__ void k_prep(const float* __restrict__ x, const float* __restrict__ W) {
    int tid = threadIdx.x;
    if (blockIdx.x < SCALE_BLOCKS) {
        int row  = blockIdx.x * 8 + (tid >> 5);
        int lane = tid & 31;
        int cnt = g_cnt[row];
        float d = (cnt > 0) ? rsqrtf((float)cnt) : 0.0f;
        int c = cnt < CAP ? cnt : CAP;
        int pe = (c + 3) & ~3;
        if (lane == 0) g_meta[row] = make_int2(pe, __float_as_int(d));
        // pad ELL row to multiple of 4 with pointers to the zero row (NN)
        if (lane < pe - c) g_ell[(size_t)row * CAP + c + lane] = NN * FF;
        int l2 = lane * 2;
        size_t idx = (size_t)row * FF + l2;
        float2 v = *(const float2*)(x + idx);
        __half2 h = __float22half2_rn(make_float2(v.x * d, v.y * d));
        *(__half2*)(g_XSh + idx) = h;
    } else {
        int idx = (blockIdx.x - SCALE_BLOCKS) * 256 + tid;  // 0..32767
        int h = idx >> 8, kidx = idx & 255;
        int k4 = kidx >> 6, f = kidx & 63;
        float w = W[k4 * (FF * HH) + f * HH + h];
        bf16 hi = __float2bfloat16(w);
        bf16 lo = __float2bfloat16(w - __bfloat162float(hi));
        g_Bhi[h * 256 + kidx] = hi;
        g_Blo[h * 256 + kidx] = lo;
    }
}

// ---------------- SPMM: TWO rows per warp, HALF planes only ------------------
// lanes 0-15 -> row 2w, lanes 16-31 -> row 2w+1; each lane owns 4 features.
// Gathers read half planes (128B/neighbor/row); f32 incremental accumulation.
// Each phase stores ONE 8-byte half result per thread (no f32 T arrays):
//   P1: T1h = half(-d^2 * S(XSh))                      [= dinv*T1]
//   P2: T2h = half(d * fma(-2d, S(T1h), -X))           [= dinv*T2]
//   P3: T3h = half(fma(-2d, S(T2h), -T1h*rdeg))        [= T3]
template <int PHASE>
__global__ __launch_bounds__(256, 8)
void k_spmm(const float* __restrict__ x) {
    int warp = (blockIdx.x * blockDim.x + threadIdx.x) >> 5;
    int lane = threadIdx.x & 31;
    int row  = warp * 2 + (lane >> 4);
    if (row >= NN) return;
    int l4 = (lane & 15) * 4;

    const __half* __restrict__ srcH = (PHASE == 1) ? g_XSh
                                    : (PHASE == 2) ? g_T1h : g_T2h;
    __half* __restrict__ dstH = (PHASE == 1) ? g_T1h
                              : (PHASE == 2) ? g_T2h : g_T3h;

    int2 mt = g_meta[row];
    int cnt4 = mt.x;
    float d = __int_as_float(mt.y);
    const int* ep = g_ell + (size_t)row * CAP;
    const __half* srcL = srcH + l4;            // lane-adjusted base

    float4 acc = make_float4(0.f, 0.f, 0.f, 0.f);
    for (int i = 0; i < cnt4; i += 4) {
        int4 c = *(const int4*)(ep + i);
        ull v0 = *(const ull*)(srcL + c.x);
        ull v1 = *(const ull*)(srcL + c.y);
        ull v2 = *(const ull*)(srcL + c.z);
        ull v3 = *(const ull*)(srcL + c.w);
        acc_h4(acc, v0);
        acc_h4(acc, v1);
        acc_h4(acc, v2);
        acc_h4(acc, v3);
    }

    size_t idx = (size_t)row * FF + l4;
    float4 res;
    if (PHASE == 1) {
        float m = -d * d;                      // store dinv*T1
        res.x = m * acc.x; res.y = m * acc.y;
        res.z = m * acc.z; res.w = m * acc.w;
    } else if (PHASE == 2) {
        float4 p = *(const float4*)(x + idx);  // prev = X (raw input, f32)
        float m = -2.f * d;
        res.x = d * fmaf(m, acc.x, -p.x);      // store dinv*T2
        res.y = d * fmaf(m, acc.y, -p.y);
        res.z = d * fmaf(m, acc.z, -p.z);
        res.w = d * fmaf(m, acc.w, -p.w);
    } else {
        float rd = (d > 0.f) ? __frcp_rn(d) : 0.f;   // rdeg = 1/dinv
        float4 p = unpack_h4(*(const ull*)(g_T1h + idx));  // prev = T1h*rdeg
        float m = -2.f * d;
        res.x = fmaf(m, acc.x, -p.x * rd);
        res.y = fmaf(m, acc.y, -p.y * rd);
        res.z = fmaf(m, acc.z, -p.z * rd);
        res.w = fmaf(m, acc.w, -p.w * rd);
    }
    *(ull*)(dstH + idx) = pack_h4(res);
}

// ---------------- HMMA GEMM + bias + tanh + final dot ------------------------
// out[n,h] = sum_k [X|T1|T2|T3][n,:] @ W[:,h] + b[h]; y[n]=sum_h tanh(out)*fw+fb
// bf16 hi/lo split: AhiBhi + AhiBlo + AloBhi. A staged from: X (f32), and the
// half planes (T1h/T2h un-scaled by rdeg, T3h raw). bf16 hi+lo represents any
// f16 value EXACTLY, so the split loses nothing beyond the f16 storage rounding.
// ALSO: re-zeros g_cnt for the next kernel_launch call (replay invariant).
#define SA 72                      // smem row stride in elements (144 B)
#define OFF_AH 0
#define OFF_AL (128 * SA * 2)      // 18432
#define OFF_BH (2 * 128 * SA * 2)
#define OFF_BL (3 * 128 * SA * 2)
#define OFF_BIAS (4 * 128 * SA * 2)        // 73728
#define OFF_FW   (OFF_BIAS + 512)
#define OFF_OUT  (OFF_FW + 512)
#define SMEM_DYN (OFF_OUT + 512)

// one K=64 chunk of MMAs: AhiBhi + AhiBlo + AloBhi over 4 k-slices
__device__ __forceinline__ void mma_chunk(char* smem, int wm, int wn, int g, int t,
                                          float (&acc)[4][4][4]) {
#pragma unroll
    for (int ks = 0; ks < 4; ks++) {
        int k0 = ks * 16;
        uint32_t af[4][4], bh[4][2], bl[4][2];
#pragma unroll
        for (int mt = 0; mt < 4; mt++) {
            int r = wm * 64 + mt * 16 + g;
            const char* p = smem + OFF_AH;
            af[mt][0] = *(const uint32_t*)(p + (r * SA + k0 + t * 2) * 2);
            af[mt][1] = *(const uint32_t*)(p + ((r + 8) * SA + k0 + t * 2) * 2);
            af[mt][2] = *(const uint32_t*)(p + (r * SA + k0 + t * 2 + 8) * 2);
            af[mt][3] = *(const uint32_t*)(p + ((r + 8) * SA + k0 + t * 2 + 8) * 2);
        }
#pragma unroll
        for (int nt = 0; nt < 4; nt++) {
            int c = wn * 32 + nt * 8 + g;
            bh[nt][0] = *(const uint32_t*)(smem + OFF_BH + (c * SA + k0 + t * 2) * 2);
            bh[nt][1] = *(const uint32_t*)(smem + OFF_BH + (c * SA + k0 + t * 2 + 8) * 2);
            bl[nt][0] = *(const uint32_t*)(smem + OFF_BL + (c * SA + k0 + t * 2) * 2);
            bl[nt][1] = *(const uint32_t*)(smem + OFF_BL + (c * SA + k0 + t * 2 + 8) * 2);
        }
#pragma unroll
        for (int mt = 0; mt < 4; mt++)
#pragma unroll
            for (int nt = 0; nt < 4; nt++)
                mma16816(acc[mt][nt][0], acc[mt][nt][1], acc[mt][nt][2], acc[mt][nt][3],
                         af[mt][0], af[mt][1], af[mt][2], af[mt][3],
                         bh[nt][0], bh[nt][1]);
#pragma unroll
        for (int mt = 0; mt < 4; mt++)
#pragma unroll
            for (int nt = 0; nt < 4; nt++)
                mma16816(acc[mt][nt][0], acc[mt][nt][1], acc[mt][nt][2], acc[mt][nt][3],
                         af[mt][0], af[mt][1], af[mt][2], af[mt][3],
                         bl[nt][0], bl[nt][1]);
#pragma unroll
        for (int mt = 0; mt < 4; mt++) {
            int r = wm * 64 + mt * 16 + g;
            const char* p = smem + OFF_AL;
            af[mt][0] = *(const uint32_t*)(p + (r * SA + k0 + t * 2) * 2);
            af[mt][1] = *(const uint32_t*)(p + ((r + 8) * SA + k0 + t * 2) * 2);
            af[mt][2] = *(const uint32_t*)(p + (r * SA + k0 + t * 2 + 8) * 2);
            af[mt][3] = *(const uint32_t*)(p + ((r + 8) * SA + k0 + t * 2 + 8) * 2);
        }
#pragma unroll
        for (int mt = 0; mt < 4; mt++)
#pragma unroll
            for (int nt = 0; nt < 4; nt++)
                mma16816(acc[mt][nt][0], acc[mt][nt][1], acc[mt][nt][2], acc[mt][nt][3],
                         af[mt][0], af[mt][1], af[mt][2], af[mt][3],
                         bh[nt][0], bh[nt][1]);
    }
}

__global__ __launch_bounds__(256)
void k_gemm(const float* __restrict__ x,
            const float* __restrict__ bias, const float* __restrict__ fw,
            const float* __restrict__ fb, float* __restrict__ y) {
    extern __shared__ char smem[];
    int tid  = threadIdx.x;
    int lane = tid & 31, wid = tid >> 5;
    int wm = wid >> 2, wn = wid & 3;        // warp grid 2x4
    int g = lane >> 2, t = lane & 3;        // mma groupID / threadID-in-group
    int rowBase = blockIdx.x * 128;

    // re-zero g_cnt for next call (only fill/prep consume it; gemm uses g_meta)
    int zi = blockIdx.x * 256 + tid;
    if (zi < NN) g_cnt[zi] = 0;

    if (tid < 128) {
        *(float*)(smem + OFF_BIAS + tid * 4) = bias[tid];
        *(float*)(smem + OFF_FW   + tid * 4) = fw[tid];
        *(float*)(smem + OFF_OUT  + tid * 4) = 0.f;
    }

    float acc[4][4][4];
#pragma unroll
    for (int a = 0; a < 4; a++)
#pragma unroll
        for (int b = 0; b < 4; b++)
#pragma unroll
            for (int c = 0; c < 4; c++) acc[a][b][c] = 0.f;

    const __half* Ah[3] = {g_T1h, g_T2h, g_T3h};

    for (int ch = 0; ch < 4; ch++) {
        __syncthreads();
        bool needR = (ch == 1) || (ch == 2);   // un-scale T1h/T2h by rdeg
#pragma unroll
        for (int rep = 0; rep < 4; rep++) {
            int u = rep * 256 + tid;
            int r = u >> 3, j = u & 7;         // row r, 8-elem group j
            int grow = rowBase + r;
            float4 a0 = make_float4(0.f, 0.f, 0.f, 0.f), a1 = a0;
            if (grow < NN) {
                if (ch == 0) {
                    const float* p = x + (size_t)grow * FF + j * 8;
                    a0 = *(const float4*)(p);
                    a1 = *(const float4*)(p + 4);
                } else {
                    const __half* p = Ah[ch - 1] + (size_t)grow * FF + j * 8;
                    ulonglong2 hv = *(const ulonglong2*)(p);
                    a0 = unpack_h4(hv.x);
                    a1 = unpack_h4(hv.y);
                    if (needR) {
                        float dv = __int_as_float(g_meta[grow].y);
                        float sc = (dv > 0.f) ? __frcp_rn(dv) : 0.f;
                        a0.x *= sc; a0.y *= sc; a0.z *= sc; a0.w *= sc;
                        a1.x *= sc; a1.y *= sc; a1.z *= sc; a1.w *= sc;
                    }
                }
            }
            uint4 vh, vl;
            split_hilo(a0.x, a0.y, vh.x, vl.x);
            split_hilo(a0.z, a0.w, vh.y, vl.y);
            split_hilo(a1.x, a1.y, vh.z, vl.z);
            split_hilo(a1.z, a1.w, vh.w, vl.w);
            *(uint4*)(smem + OFF_AH + r * 144 + j * 16) = vh;
            *(uint4*)(smem + OFF_AL + r * 144 + j * 16) = vl;
            uint4 bh = *(const uint4*)(g_Bhi + r * 256 + ch * 64 + j * 8);
            uint4 bl = *(const uint4*)(g_Blo + r * 256 + ch * 64 + j * 8);
            *(uint4*)(smem + OFF_BH + r * 144 + j * 16) = bh;
            *(uint4*)(smem + OFF_BL + r * 144 + j * 16) = bl;
        }
        __syncthreads();
        mma_chunk(smem, wm, wn, g, t, acc);
    }
    __syncthreads();

    // epilogue: tanh(acc + bias) * fw, reduce cols -> sm_out rows
    const float* sBias = (const float*)(smem + OFF_BIAS);
    const float* sFw   = (const float*)(smem + OFF_FW);
    float* sOut        = (float*)(smem + OFF_OUT);
#pragma unroll
    for (int mt = 0; mt < 4; mt++) {
#pragma unroll
        for (int rr = 0; rr < 2; rr++) {
            int rloc = wm * 64 + mt * 16 + g + rr * 8;
            float p = 0.f;
#pragma unroll
            for (int nt = 0; nt < 4; nt++) {
#pragma unroll
                for (int cc = 0; cc < 2; cc++) {
                    int col = wn * 32 + nt * 8 + t * 2 + cc;
                    float v = acc[mt][nt][rr * 2 + cc];
                    p += tanh_ap(v + sBias[col]) * sFw[col];
                }
            }
            p += __shfl_xor_sync(0xffffffffu, p, 1);
            p += __shfl_xor_sync(0xffffffffu, p, 2);
            if (t == 0) atomicAdd(&sOut[rloc], p);
        }
    }
    __syncthreads();
    if (tid < 128) {
        int r = rowBase + tid;
        if (r < NN) y[r] = sOut[tid] + fb[0];
    }
}

// ---------------- launch -----------------------------------------------------
extern "C" void kernel_launch(void* const* d_in, const int* in_sizes, int n_in,
                              void* d_out, int out_size) {
    const float* features = (const float*)d_in[0];
    const int*   ei       = (const int*)d_in[1];
    const float* cheb_w   = (const float*)d_in[2];
    const float* cheb_b   = (const float*)d_in[3];
    const float* final_w  = (const float*)d_in[4];
    const float* final_b  = (const float*)d_in[5];
    float* y = (float*)d_out;

    static bool attr_set = false;
    if (!attr_set) {
        cudaFuncSetAttribute(k_gemm, cudaFuncAttributeMaxDynamicSharedMemorySize,
                             SMEM_DYN);
        attr_set = true;
    }

    k_fill<<<(EE + 255) / 256, 256>>>(ei);
    k_prep<<<SCALE_BLOCKS + 128, 256>>>(features, cheb_w);

    int spmm_blocks = (NN / 2 + 7) / 8;      // 2 rows per warp, 8 warps per block
    k_spmm<1><<<spmm_blocks, 256>>>(features);
    k_spmm<2><<<spmm_blocks, 256>>>(features);   // profiled slot (4th launch)
    k_spmm<3><<<spmm_blocks, 256>>>(features);

    k_gemm<<<(NN + 127) / 128, 256, SMEM_DYN>>>(features, cheb_b, final_w,
                                                final_b, y);
}